// round 15
// baseline (speedup 1.0000x reference)
#include <cuda_runtime.h>
#include <cuda_bf16.h>
#include <math.h>

#define BB   8
#define TT   2048
#define DIN  1024
#define HH   64
#define BT   (BB*TT)
#define PST  36      // attn smem row stride in u32 (144B) -> conflict-free ldmatrix

typedef unsigned int u32;

// K pre-scale: (1/8) * log2(e)  -> softmax computed in exp2 domain
#define KSCALE 0.18033688f

// Packed bf16x2 hi/lo scratch (q,k) and transposed v, prepped weights.
__device__ __align__(16) u32 g_qh[BT*32];
__device__ __align__(16) u32 g_ql[BT*32];
__device__ __align__(16) u32 g_kh[BT*32];
__device__ __align__(16) u32 g_kl[BT*32];
// V transposed: [b][h 0..63][sp 0..1023], u32 = pack(v[2sp][h], v[2sp+1][h])
__device__ __align__(16) u32 g_vth[BB*64*1024];
__device__ __align__(16) u32 g_vtl[BB*64*1024];
// W fragment-ready: [n 0..191][kk 0..511] u32 = pack(W[2kk][n], W[2kk+1][n])
__device__ __align__(16) u32 g_wh[192*512];
__device__ __align__(16) u32 g_wl[192*512];

// ---- helpers ---------------------------------------------------------------
__device__ __forceinline__ u32 pkbf(float lo, float hi) {
    u32 r; asm("cvt.rn.bf16x2.f32 %0, %1, %2;" : "=r"(r) : "f"(hi), "f"(lo));
    return r;
}
__device__ __forceinline__ float bfh(float x) {
    return __bfloat162float(__float2bfloat16(x));
}
__device__ __forceinline__ float ex2(float x) {
    float r; asm("ex2.approx.f32 %0, %1;" : "=f"(r) : "f"(x)); return r;
}
__device__ __forceinline__ void mma16816(float* c, const u32* a, const u32* b) {
    asm volatile(
        "mma.sync.aligned.m16n8k16.row.col.f32.bf16.bf16.f32 "
        "{%0,%1,%2,%3}, {%4,%5,%6,%7}, {%8,%9}, {%0,%1,%2,%3};"
        : "+f"(c[0]), "+f"(c[1]), "+f"(c[2]), "+f"(c[3])
        : "r"(a[0]), "r"(a[1]), "r"(a[2]), "r"(a[3]), "r"(b[0]), "r"(b[1]));
}
__device__ __forceinline__ void ldm_x4(u32* r, u32 addr) {
    asm volatile("ldmatrix.sync.aligned.m8n8.x4.shared.b16 {%0,%1,%2,%3}, [%4];"
        : "=r"(r[0]), "=r"(r[1]), "=r"(r[2]), "=r"(r[3]) : "r"(addr));
}
__device__ __forceinline__ void ldm_x2(u32* r, u32 addr) {
    asm volatile("ldmatrix.sync.aligned.m8n8.x2.shared.b16 {%0,%1}, [%2];"
        : "=r"(r[0]), "=r"(r[1]) : "r"(addr));
}
__device__ __forceinline__ void cp16(u32 smem, const void* g) {
    asm volatile("cp.async.cg.shared.global [%0], [%1], 16;" :: "r"(smem), "l"(g));
}
__device__ __forceinline__ void cp_commit() {
    asm volatile("cp.async.commit_group;" ::: "memory");
}
__device__ __forceinline__ void cp_wait0() {
    asm volatile("cp.async.wait_group 0;" ::: "memory");
}
__device__ __forceinline__ u32 smem_u32(const void* p) {
    u32 a;
    asm("{ .reg .u64 t; cvta.to.shared.u64 t, %1; cvt.u32.u64 %0, t; }"
        : "=r"(a) : "l"(p));
    return a;
}

// ---------------------------------------------------------------------------
// Prep: W -> bf16 hi/lo packed, fragment-ready. Coalesced via smem transpose.
// ---------------------------------------------------------------------------
__global__ __launch_bounds__(256) void prep_w_kernel(
    const float* __restrict__ Wq, const float* __restrict__ Wk,
    const float* __restrict__ Wv)
{
    __shared__ float wt[64][65];
    const int mat = blockIdx.x / 16;
    const int kb  = blockIdx.x % 16;
    const float* W = (mat == 0) ? Wq : ((mat == 1) ? Wk : Wv);
    const int tid = threadIdx.x;

    #pragma unroll
    for (int u = 0; u < 4; u++) {
        int idx = tid + u * 256;
        int row = idx >> 4, c4 = (idx & 15) << 2;
        float4 v = *(const float4*)(W + (size_t)(kb * 64 + row) * HH + c4);
        wt[row][c4]     = v.x; wt[row][c4 + 1] = v.y;
        wt[row][c4 + 2] = v.z; wt[row][c4 + 3] = v.w;
    }
    __syncthreads();

    #pragma unroll
    for (int u = 0; u < 8; u++) {
        int idx = tid + u * 256;
        int n = idx >> 5, pj = idx & 31;
        float w0 = wt[2 * pj][n], w1 = wt[2 * pj + 1][n];
        float h0 = bfh(w0), h1 = bfh(w1);
        size_t off = (size_t)(mat * 64 + n) * 512 + kb * 32 + pj;
        g_wh[off] = pkbf(h0, h1);
        g_wl[off] = pkbf(w0 - h0, w1 - h1);
    }
}

// ---------------------------------------------------------------------------
// Fused QKV projection (unchanged from R14): M=128 x N=192, K-chunk 64,
// grid(128) x 512, LDG-prefetch X + in-body convert, one barrier per iter.
// ---------------------------------------------------------------------------
#define XPK(pb)  ((pb) * 9216)
#define PW(pb)   (18432 + (pb) * 13824)
#define WSTR  36
#define PROJ_SMEM_U32 46080

__device__ __forceinline__ void stageW64(u32 sbyte, const u32* g, int tid) {
    #pragma unroll
    for (int u = 0; u < 3; u++) {
        int idx = tid + u * 512;
        int row = idx >> 3, ch = idx & 7;
        cp16(sbyte + (u32)(row * WSTR + ch * 4) * 4, g + (size_t)row * 512 + ch * 4);
    }
}
__device__ __forceinline__ void ldgX(float4 (&v)[4], const float* g, int row, int g3) {
    const float* src = g + (size_t)row * DIN + g3 * 16;
    v[0] = *(const float4*)(src);
    v[1] = *(const float4*)(src + 4);
    v[2] = *(const float4*)(src + 8);
    v[3] = *(const float4*)(src + 12);
}
__device__ __forceinline__ void convertX(u32* sxh, u32* sxl, const float4 (&v)[4],
                                         int row, int g3) {
    #pragma unroll
    for (int j = 0; j < 4; j++) {
        float h0 = bfh(v[j].x), h1 = bfh(v[j].y), h2 = bfh(v[j].z), h3 = bfh(v[j].w);
        sxh[row * WSTR + g3 * 8 + 2 * j]     = pkbf(h0, h1);
        sxh[row * WSTR + g3 * 8 + 2 * j + 1] = pkbf(h2, h3);
        sxl[row * WSTR + g3 * 8 + 2 * j]     = pkbf(v[j].x - h0, v[j].y - h1);
        sxl[row * WSTR + g3 * 8 + 2 * j + 1] = pkbf(v[j].z - h2, v[j].w - h3);
    }
}

__global__ __launch_bounds__(512) void proj_kernel(const float* __restrict__ x)
{
    extern __shared__ u32 sm[];
    const u32 sbx = smem_u32(sm);
    const int tid  = threadIdx.x;
    const int lane = tid & 31;
    const int wid  = tid >> 5;
    const int slab = wid >> 2, qc = wid & 3;
    const int rr   = lane >> 2, q = lane & 3;
    const int m0   = blockIdx.x * 128;

    const int lane7 = lane & 7;
    const int arow  = lane7 + (lane & 8);
    const int acx4  = (lane & 16) ? 16 : 0;
    const int bex4  = (lane & 8) ? 16 : 0;
    const int xrow  = tid >> 2, xg3 = tid & 3;

    stageW64(sbx + (u32)PW(0) * 4,            g_wh, tid);
    stageW64(sbx + (u32)(PW(0) + 6912) * 4,   g_wl, tid);
    cp_commit();
    {
        float4 xr0[4];
        ldgX(xr0, x + (size_t)m0 * DIN, xrow, xg3);
        convertX(sm + XPK(0), sm + XPK(0) + 4608, xr0, xrow, xg3);
    }
    cp_wait0();
    __syncthreads();

    float acc[2][6][4];
    #pragma unroll
    for (int mt = 0; mt < 2; mt++)
        #pragma unroll
        for (int i = 0; i < 6; i++)
            #pragma unroll
            for (int j = 0; j < 4; j++) acc[mt][i][j] = 0.f;

    float4 xr[4];
    for (int c = 0; c < 16; c++) {
        const int pb = c & 1;
        if (c < 15) {
            stageW64(sbx + (u32)PW(pb ^ 1) * 4,          g_wh + (c + 1) * 32, tid);
            stageW64(sbx + (u32)(PW(pb ^ 1) + 6912) * 4, g_wl + (c + 1) * 32, tid);
            cp_commit();
            ldgX(xr, x + (size_t)m0 * DIN + (c + 1) * 64, xrow, xg3);
        }

        const u32 xb = (u32)XPK(pb);
        const u32 wb = (u32)PW(pb);
        u32 aH[2], aL[2];
        #pragma unroll
        for (int mt = 0; mt < 2; mt++) {
            aH[mt] = sbx + (xb + (slab * 32 + mt * 16 + arow) * WSTR) * 4 + acx4;
            aL[mt] = aH[mt] + 4608 * 4;
        }
        const u32 bH = sbx + (wb + (qc * 48 + lane7) * WSTR) * 4 + bex4;
        const u32 bL = bH + 6912 * 4;

        #pragma unroll
        for (int kt = 0; kt < 4; kt++) {
            u32 ah0[4], al0[4], ah1[4], al1[4];
            ldm_x4(ah0, aH[0] + kt * 32);
            ldm_x4(al0, aL[0] + kt * 32);
            ldm_x4(ah1, aH[1] + kt * 32);
            ldm_x4(al1, aL[1] + kt * 32);
            #pragma unroll
            for (int nt = 0; nt < 6; nt++) {
                u32 bh[2], bl[2];
                ldm_x2(bh, bH + nt * (8 * WSTR * 4) + kt * 32);
                ldm_x2(bl, bL + nt * (8 * WSTR * 4) + kt * 32);
                mma16816(acc[0][nt], ah0, bh);
                mma16816(acc[0][nt], ah0, bl);
                mma16816(acc[0][nt], al0, bh);
                mma16816(acc[1][nt], ah1, bh);
                mma16816(acc[1][nt], ah1, bl);
                mma16816(acc[1][nt], al1, bh);
            }
        }

        if (c < 15) {
            convertX(sm + XPK(pb ^ 1), sm + XPK(pb ^ 1) + 4608, xr, xrow, xg3);
            cp_wait0();
        }
        __syncthreads();
    }

    // epilogue: q/k packed rows; v written directly transposed (shfl-paired)
    u32* const GH[2] = {g_qh, g_kh};
    u32* const GL[2] = {g_ql, g_kl};
    #pragma unroll
    for (int mt = 0; mt < 2; mt++) {
        const int row0 = m0 + slab * 32 + mt * 16 + rr;
        #pragma unroll
        for (int nt = 0; nt < 6; nt++) {
            int colb = qc * 48 + nt * 8;
            int mat = colb >> 6;
            float a0 = acc[mt][nt][0], a1 = acc[mt][nt][1];
            float a2 = acc[mt][nt][2], a3 = acc[mt][nt][3];
            if (mat < 2) {
                float s = (mat == 1) ? KSCALE : 1.f;
                a0 *= s; a1 *= s; a2 *= s; a3 *= s;
                int hqb = (colb & 63) >> 1;
                float h0 = bfh(a0), h1 = bfh(a1), h2 = bfh(a2), h3 = bfh(a3);
                GH[mat][(size_t)row0 * 32 + hqb + q]       = pkbf(h0, h1);
                GL[mat][(size_t)row0 * 32 + hqb + q]       = pkbf(a0 - h0, a1 - h1);
                GH[mat][(size_t)(row0 + 8) * 32 + hqb + q] = pkbf(h2, h3);
                GL[mat][(size_t)(row0 + 8) * 32 + hqb + q] = pkbf(a2 - h2, a3 - h3);
            } else {
                float p0 = __shfl_xor_sync(0xffffffffu, a0, 4);
                float p1 = __shfl_xor_sync(0xffffffffu, a1, 4);
                float p2 = __shfl_xor_sync(0xffffffffu, a2, 4);
                float p3 = __shfl_xor_sync(0xffffffffu, a3, 4);
                if (!(rr & 1)) {
                    int bb2 = row0 >> 11;
                    int sp  = (row0 & 2047) >> 1;
                    int vc  = (colb - 128) + 2 * q;
                    size_t base0 = ((size_t)(bb2 * 64 + vc)) * 1024;
                    size_t base1 = base0 + 1024;
                    float h, hp;
                    h = bfh(a0); hp = bfh(p0);
                    g_vth[base0 + sp] = pkbf(h, hp);
                    g_vtl[base0 + sp] = pkbf(a0 - h, p0 - hp);
                    h = bfh(a1); hp = bfh(p1);
                    g_vth[base1 + sp] = pkbf(h, hp);
                    g_vtl[base1 + sp] = pkbf(a1 - h, p1 - hp);
                    h = bfh(a2); hp = bfh(p2);
                    g_vth[base0 + sp + 4] = pkbf(h, hp);
                    g_vtl[base0 + sp + 4] = pkbf(a2 - h, p2 - hp);
                    h = bfh(a3); hp = bfh(p3);
                    g_vth[base1 + sp + 4] = pkbf(h, hp);
                    g_vtl[base1 + sp + 4] = pkbf(a3 - h, p3 - hp);
                }
            }
        }
    }
}

// ---------------------------------------------------------------------------
// Flash attention: 128-thread CTAs, 2 per SM. CTA = (pair bx, row-half rh, b):
// handles 32 t-rows of tiles (bx, 31-bx). 4 warps = 2 slabs x 2 col-halves.
// smem (u32): K 0..4608 | Q 4608..13824 | V 13824..23040 | mlbuf 23040..23168
// obuf aliases Q region (used only after the loop). 92672 B per CTA.
// ---------------------------------------------------------------------------
#define AKOFF(t, l)  ((t) * 2304 + (l) * 1152)
#define AQOFF(bf, l) (4608 + (bf) * 4608 + (l) * 2304)
#define AVOFF(bf, l) (13824 + (bf) * 4608 + (l) * 2304)
#define ATTN_SMEM_U32 23168   // 92672 B

// 64-row staging with 128 threads (512 chunks)
__device__ __forceinline__ void stage64n(u32 sbyte, const u32* g, int gstride, int tid) {
    #pragma unroll
    for (int u = 0; u < 4; u++) {
        int idx = tid + u * 128;
        int row = idx >> 3, ch = idx & 7;
        cp16(sbyte + (u32)(row * PST + ch * 4) * 4, g + (size_t)row * gstride + ch * 4);
    }
}
// 32-row staging with 128 threads (256 chunks)
__device__ __forceinline__ void stage32n(u32 sbyte, const u32* g, int gstride, int tid) {
    #pragma unroll
    for (int u = 0; u < 2; u++) {
        int idx = tid + u * 128;
        int row = idx >> 3, ch = idx & 7;
        cp16(sbyte + (u32)(row * PST + ch * 4) * 4, g + (size_t)row * gstride + ch * 4);
    }
}

__device__ __forceinline__ void online_update(
    float (&sacc)[4][4], float& m_lo, float& m_hi, float& l_lo, float& l_hi,
    float (&o)[8][4], u32 (&pah)[2][4], u32 (&pal)[2][4])
{
    float mx0 = -INFINITY, mx1 = -INFINITY;
    #pragma unroll
    for (int nt = 0; nt < 4; nt++) {
        mx0 = fmaxf(mx0, fmaxf(sacc[nt][0], sacc[nt][1]));
        mx1 = fmaxf(mx1, fmaxf(sacc[nt][2], sacc[nt][3]));
    }
    mx0 = fmaxf(mx0, __shfl_xor_sync(0xffffffffu, mx0, 1));
    mx0 = fmaxf(mx0, __shfl_xor_sync(0xffffffffu, mx0, 2));
    mx1 = fmaxf(mx1, __shfl_xor_sync(0xffffffffu, mx1, 1));
    mx1 = fmaxf(mx1, __shfl_xor_sync(0xffffffffu, mx1, 2));
    float mn0 = fmaxf(m_lo, mx0), mn1 = fmaxf(m_hi, mx1);
    float sum0 = 0.f, sum1 = 0.f;
    #pragma unroll
    for (int nt = 0; nt < 4; nt++) {
        sacc[nt][0] = ex2(fmaxf(sacc[nt][0] - mn0, -126.f));
        sacc[nt][1] = ex2(fmaxf(sacc[nt][1] - mn0, -126.f));
        sacc[nt][2] = ex2(fmaxf(sacc[nt][2] - mn1, -126.f));
        sacc[nt][3] = ex2(fmaxf(sacc[nt][3] - mn1, -126.f));
        sum0 += sacc[nt][0] + sacc[nt][1];
        sum1 += sacc[nt][2] + sacc[nt][3];
    }
    sum0 += __shfl_xor_sync(0xffffffffu, sum0, 1);
    sum0 += __shfl_xor_sync(0xffffffffu, sum0, 2);
    sum1 += __shfl_xor_sync(0xffffffffu, sum1, 1);
    sum1 += __shfl_xor_sync(0xffffffffu, sum1, 2);
    float cf0 = ex2(fmaxf(m_lo - mn0, -126.f));
    float cf1 = ex2(fmaxf(m_hi - mn1, -126.f));
    l_lo = l_lo * cf0 + sum0; l_hi = l_hi * cf1 + sum1;
    m_lo = mn0; m_hi = mn1;
    #pragma unroll
    for (int nt = 0; nt < 8; nt++) {
        o[nt][0] *= cf0; o[nt][1] *= cf0;
        o[nt][2] *= cf1; o[nt][3] *= cf1;
    }
    #pragma unroll
    for (int kp = 0; kp < 2; kp++) {
        float p00 = sacc[2*kp][0],   p01 = sacc[2*kp][1];
        float p02 = sacc[2*kp][2],   p03 = sacc[2*kp][3];
        float p10 = sacc[2*kp+1][0], p11 = sacc[2*kp+1][1];
        float p12 = sacc[2*kp+1][2], p13 = sacc[2*kp+1][3];
        float h00 = bfh(p00), h01 = bfh(p01), h02 = bfh(p02), h03 = bfh(p03);
        float h10 = bfh(p10), h11 = bfh(p11), h12 = bfh(p12), h13 = bfh(p13);
        pah[kp][0] = pkbf(h00, h01);
        pah[kp][1] = pkbf(h02, h03);
        pah[kp][2] = pkbf(h10, h11);
        pah[kp][3] = pkbf(h12, h13);
        pal[kp][0] = pkbf(p00 - h00, p01 - h01);
        pal[kp][1] = pkbf(p02 - h02, p03 - h03);
        pal[kp][2] = pkbf(p10 - h10, p11 - h11);
        pal[kp][3] = pkbf(p12 - h12, p13 - h13);
    }
}

__device__ __forceinline__ void merge_write(
    float (&o)[8][4], float m_lo, float m_hi, float l_lo, float l_hi,
    float* mlbuf, float* obuf, int slab, int half, int rr, int q,
    float* __restrict__ out, int b, int t0)
{
    __syncthreads();
    if (q == 0) {
        int base = (slab * 2 + half) * 16;
        mlbuf[(base + rr) * 2]         = m_lo;
        mlbuf[(base + rr) * 2 + 1]     = l_lo;
        mlbuf[(base + rr + 8) * 2]     = m_hi;
        mlbuf[(base + rr + 8) * 2 + 1] = l_hi;
    }
    __syncthreads();
    int ob = (slab * 2 + (1 - half)) * 16;
    float mo0 = mlbuf[(ob + rr) * 2],     lo0 = mlbuf[(ob + rr) * 2 + 1];
    float mo1 = mlbuf[(ob + rr + 8) * 2], lo1 = mlbuf[(ob + rr + 8) * 2 + 1];
    float M0 = fmaxf(m_lo, mo0), M1 = fmaxf(m_hi, mo1);
    float f0 = ex2(fmaxf(m_lo - M0, -126.f));
    float f1 = ex2(fmaxf(m_hi - M1, -126.f));
    float g0 = ex2(fmaxf(mo0 - M0, -126.f));
    float g1 = ex2(fmaxf(mo1 - M1, -126.f));
    float L0 = l_lo * f0 + lo0 * g0;
    float L1 = l_hi * f1 + lo1 * g1;
    #pragma unroll
    for (int nt = 0; nt < 8; nt++) {
        o[nt][0] *= f0; o[nt][1] *= f0;
        o[nt][2] *= f1; o[nt][3] *= f1;
    }
    if (half == 1) {
        #pragma unroll
        for (int nt = 0; nt < 8; nt++) {
            int cb = nt * 8 + 2 * q;
            obuf[(slab * 16 + rr) * 64 + cb]         = o[nt][0];
            obuf[(slab * 16 + rr) * 64 + cb + 1]     = o[nt][1];
            obuf[(slab * 16 + rr + 8) * 64 + cb]     = o[nt][2];
            obuf[(slab * 16 + rr + 8) * 64 + cb + 1] = o[nt][3];
        }
    }
    __syncthreads();
    if (half == 0) {
        float i0 = 1.f / L0, i1 = 1.f / L1;
        size_t rb = ((size_t)b * TT + t0 + slab * 16 + rr) * 64;
        #pragma unroll
        for (int nt = 0; nt < 8; nt++) {
            int cb = nt * 8 + 2 * q;
            float2 r1;
            r1.x = (o[nt][0] + obuf[(slab * 16 + rr) * 64 + cb]) * i0;
            r1.y = (o[nt][1] + obuf[(slab * 16 + rr) * 64 + cb + 1]) * i0;
            *(float2*)(out + rb + cb) = r1;
            float2 r2;
            r2.x = (o[nt][2] + obuf[(slab * 16 + rr + 8) * 64 + cb]) * i1;
            r2.y = (o[nt][3] + obuf[(slab * 16 + rr + 8) * 64 + cb + 1]) * i1;
            *(float2*)(out + rb + 8 * 64 + cb) = r2;
        }
    }
}

__global__ __launch_bounds__(128, 2) void attn_kernel(float* __restrict__ out)
{
    extern __shared__ u32 sm[];
    float* mlbuf = (float*)(sm + 23040);
    float* obuf  = (float*)(sm + 4608);     // aliases Q region (post-loop only)

    const int tid  = threadIdx.x;
    const int wid  = tid >> 5, lane = tid & 31;
    const int slab = wid >> 1, half = wid & 1;   // slab 0..1, half 0..1
    const int rr   = lane >> 2, q = lane & 3;
    const int b    = blockIdx.y;
    const int bx   = blockIdx.x >> 1;            // pair index 0..15
    const int rh   = blockIdx.x & 1;             // row-half of both tiles
    const int tB   = 31 - bx;
    const int last = tB;

    const u32 sb = smem_u32(sm);
    const int lane7 = lane & 7;
    const int arow  = lane7 + (lane & 8);
    const int acx4  = (lane & 16) ? 16 : 0;
    const int bex4  = (lane & 8) ? 16 : 0;

    // stage K halves (both tiles) + Q/V(st=0)
    stage32n(sb + (u32)AKOFF(0,0) * 4, g_kh + ((size_t)b * TT + bx * 64 + rh * 32) * 32, 32, tid);
    stage32n(sb + (u32)AKOFF(0,1) * 4, g_kl + ((size_t)b * TT + bx * 64 + rh * 32) * 32, 32, tid);
    stage32n(sb + (u32)AKOFF(1,0) * 4, g_kh + ((size_t)b * TT + tB * 64 + rh * 32) * 32, 32, tid);
    stage32n(sb + (u32)AKOFF(1,1) * 4, g_kl + ((size_t)b * TT + tB * 64 + rh * 32) * 32, 32, tid);
    stage64n(sb + (u32)AQOFF(0,0) * 4, g_qh + (size_t)b * TT * 32, 32, tid);
    stage64n(sb + (u32)AQOFF(0,1) * 4, g_ql + (size_t)b * TT * 32, 32, tid);
    stage64n(sb + (u32)AVOFF(0,0) * 4, g_vth + (size_t)b * 65536, 1024, tid);
    stage64n(sb + (u32)AVOFF(0,1) * 4, g_vtl + (size_t)b * 65536, 1024, tid);
    cp_commit();
    cp_wait0();
    __syncthreads();

    // hoist K fragments to registers: [tile][hl][kt][4]
    u32 kf[2][2][4][4];
    #pragma unroll
    for (int t = 0; t < 2; t++)
        #pragma unroll
        for (int l = 0; l < 2; l++) {
            u32 base = sb + (u32)(AKOFF(t,l) + (slab * 16 + arow) * PST) * 4 + acx4;
            #pragma unroll
            for (int kt = 0; kt < 4; kt++)
                ldm_x4(kf[t][l][kt], base + kt * 32);
        }

    float oA[8][4], oB[8][4];
    #pragma unroll
    for (int i = 0; i < 8; i++)
        #pragma unroll
        for (int j = 0; j < 4; j++) { oA[i][j] = 0.f; oB[i][j] = 0.f; }
    float mA0 = -INFINITY, mA1 = -INFINITY, lA0 = 0.f, lA1 = 0.f;
    float mB0 = -INFINITY, mB1 = -INFINITY, lB0 = 0.f, lB1 = 0.f;

    for (int st = 0; st <= last; st++) {
        const int buf = st & 1;
        if (st > 0) { cp_wait0(); __syncthreads(); }
        if (st < last) {
            int nb = buf ^ 1, s1 = st + 1;
            stage64n(sb + (u32)AQOFF(nb,0) * 4, g_qh + ((size_t)b * TT + s1 * 64) * 32, 32, tid);
            stage64n(sb + (u32)AQOFF(nb,1) * 4, g_ql + ((size_t)b * TT + s1 * 64) * 32, 32, tid);
            stage64n(sb + (u32)AVOFF(nb,0) * 4, g_vth + (size_t)b * 65536 + s1 * 32, 1024, tid);
            stage64n(sb + (u32)AVOFF(nb,1) * 4, g_vtl + (size_t)b * 65536 + s1 * 32, 1024, tid);
            cp_commit();
        }
        const bool actA = (st <= bx);
        const u32 qB  = sb + (u32)(AQOFF(buf,0) + (half * 32 + lane7) * PST) * 4 + bex4;
        const u32 qBl = qB + 2304 * 4;
        const u32 vB  = sb + (u32)(AVOFF(buf,0) + lane7 * PST + half * 16) * 4 + bex4;
        const u32 vBl = vB + 2304 * 4;

        // ---- S for both tiles (K from registers) ----
        float sA[4][4], sB4[4][4];
        #pragma unroll
        for (int i = 0; i < 4; i++)
            #pragma unroll
            for (int j = 0; j < 4; j++) { sA[i][j] = 0.f; sB4[i][j] = 0.f; }
        #pragma unroll
        for (int kt = 0; kt < 4; kt++) {
            #pragma unroll
            for (int nt = 0; nt < 4; nt++) {
                u32 bh[2], bl[2];
                ldm_x2(bh, qB  + nt * (8 * PST * 4) + kt * 32);
                ldm_x2(bl, qBl + nt * (8 * PST * 4) + kt * 32);
                if (actA) {
                    mma16816(sA[nt], kf[0][0][kt], bh);
                    mma16816(sA[nt], kf[0][0][kt], bl);
                    mma16816(sA[nt], kf[0][1][kt], bh);
                }
                mma16816(sB4[nt], kf[1][0][kt], bh);
                mma16816(sB4[nt], kf[1][0][kt], bl);
                mma16816(sB4[nt], kf[1][1][kt], bh);
            }
        }

        const int s0 = st * 64;
        u32 pahA[2][4], palA[2][4], pahB[2][4], palB[2][4];
        if (actA) {
            if (st == bx) {
                int tlo = bx * 64 + rh * 32 + slab * 16 + rr, thi = tlo + 8;
                #pragma unroll
                for (int nt = 0; nt < 4; nt++) {
                    int sc = s0 + half * 32 + nt * 8 + 2 * q;
                    if (sc > tlo)     sA[nt][0] = -INFINITY;
                    if (sc + 1 > tlo) sA[nt][1] = -INFINITY;
                    if (sc > thi)     sA[nt][2] = -INFINITY;
                    if (sc + 1 > thi) sA[nt][3] = -INFINITY;
                }
            }
            online_update(sA, mA0, mA1, lA0, lA1, oA, pahA, palA);
        }
        if (st == tB) {
            int tlo = tB * 64 + rh * 32 + slab * 16 + rr, thi = tlo + 8;
            #pragma unroll
            for (int nt = 0; nt < 4; nt++) {
                int sc = s0 + half * 32 + nt * 8 + 2 * q;
                if (sc > tlo)     sB4[nt][0] = -INFINITY;
                if (sc + 1 > tlo) sB4[nt][1] = -INFINITY;
                if (sc > thi)     sB4[nt][2] = -INFINITY;
                if (sc + 1 > thi) sB4[nt][3] = -INFINITY;
            }
        }
        online_update(sB4, mB0, mB1, lB0, lB1, oB, pahB, palB);

        // ---- O += P.V (V fragments shared between tiles) ----
        #pragma unroll
        for (int kp = 0; kp < 2; kp++) {
            #pragma unroll
            for (int nt = 0; nt < 8; nt++) {
                u32 vh2[2], vl2[2];
                ldm_x2(vh2, vB  + nt * (8 * PST * 4) + kp * 32);
                ldm_x2(vl2, vBl + nt * (8 * PST * 4) + kp * 32);
                if (actA) {
                    mma16816(oA[nt], pahA[kp], vh2);
                    mma16816(oA[nt], pahA[kp], vl2);
                    mma16816(oA[nt], palA[kp], vh2);
                }
                mma16816(oB[nt], pahB[kp], vh2);
                mma16816(oB[nt], pahB[kp], vl2);
                mma16816(oB[nt], palB[kp], vh2);
            }
        }
    }

    merge_write(oA, mA0, mA1, lA0, lA1, mlbuf, obuf, slab, half, rr, q, out, b,
                bx * 64 + rh * 32);
    merge_write(oB, mB0, mB1, lB0, lB1, mlbuf, obuf, slab, half, rr, q, out, b,
                tB * 64 + rh * 32);
}

// ---------------------------------------------------------------------------
extern "C" void kernel_launch(void* const* d_in, const int* in_sizes, int n_in,
                              void* d_out, int out_size)
{
    const float* x  = (const float*)d_in[0];
    const float* Wq = (const float*)d_in[1];
    const float* Wk = (const float*)d_in[2];
    const float* Wv = (const float*)d_in[3];
    float* out = (float*)d_out;

    prep_w_kernel<<<48, 256>>>(Wq, Wk, Wv);

    cudaFuncSetAttribute(proj_kernel,
                         cudaFuncAttributeMaxDynamicSharedMemorySize,
                         PROJ_SMEM_U32 * 4);
    proj_kernel<<<128, 512, PROJ_SMEM_U32 * 4>>>(x);

    cudaFuncSetAttribute(attn_kernel,
                         cudaFuncAttributeMaxDynamicSharedMemorySize,
                         ATTN_SMEM_U32 * 4);
    dim3 grid(32, BB);
    attn_kernel<<<grid, 128, ATTN_SMEM_U32 * 4>>>(out);
}

// round 16
// speedup vs baseline: 1.6981x; 1.6981x over previous
#include <cuda_runtime.h>
#include <cuda_bf16.h>
#include <math.h>

#define BB   8
#define TT   2048
#define DIN  1024
#define HH   64
#define BT   (BB*TT)
#define PST  36      // attn smem row stride in u32 (144B) -> conflict-free ldmatrix

typedef unsigned int u32;

// K pre-scale: (1/8) * log2(e)  -> softmax computed in exp2 domain
#define KSCALE 0.18033688f

// Packed bf16x2 hi/lo scratch (q,k) and transposed v, prepped weights.
__device__ __align__(16) u32 g_qh[BT*32];
__device__ __align__(16) u32 g_ql[BT*32];
__device__ __align__(16) u32 g_kh[BT*32];
__device__ __align__(16) u32 g_kl[BT*32];
// V transposed: [b][h 0..63][sp 0..1023], u32 = pack(v[2sp][h], v[2sp+1][h])
__device__ __align__(16) u32 g_vth[BB*64*1024];
__device__ __align__(16) u32 g_vtl[BB*64*1024];
// W fragment-ready: [n 0..191][kk 0..511] u32 = pack(W[2kk][n], W[2kk+1][n])
__device__ __align__(16) u32 g_wh[192*512];
__device__ __align__(16) u32 g_wl[192*512];

// ---- helpers ---------------------------------------------------------------
__device__ __forceinline__ u32 pkbf(float lo, float hi) {
    u32 r; asm("cvt.rn.bf16x2.f32 %0, %1, %2;" : "=r"(r) : "f"(hi), "f"(lo));
    return r;
}
__device__ __forceinline__ float bfh(float x) {
    return __bfloat162float(__float2bfloat16(x));
}
__device__ __forceinline__ float ex2(float x) {
    float r; asm("ex2.approx.f32 %0, %1;" : "=f"(r) : "f"(x)); return r;
}
__device__ __forceinline__ void mma16816(float* c, const u32* a, const u32* b) {
    asm volatile(
        "mma.sync.aligned.m16n8k16.row.col.f32.bf16.bf16.f32 "
        "{%0,%1,%2,%3}, {%4,%5,%6,%7}, {%8,%9}, {%0,%1,%2,%3};"
        : "+f"(c[0]), "+f"(c[1]), "+f"(c[2]), "+f"(c[3])
        : "r"(a[0]), "r"(a[1]), "r"(a[2]), "r"(a[3]), "r"(b[0]), "r"(b[1]));
}
__device__ __forceinline__ void ldm_x4(u32* r, u32 addr) {
    asm volatile("ldmatrix.sync.aligned.m8n8.x4.shared.b16 {%0,%1,%2,%3}, [%4];"
        : "=r"(r[0]), "=r"(r[1]), "=r"(r[2]), "=r"(r[3]) : "r"(addr));
}
__device__ __forceinline__ void cp16(u32 smem, const void* g) {
    asm volatile("cp.async.cg.shared.global [%0], [%1], 16;" :: "r"(smem), "l"(g));
}
__device__ __forceinline__ void cp_commit() {
    asm volatile("cp.async.commit_group;" ::: "memory");
}
__device__ __forceinline__ void cp_wait0() {
    asm volatile("cp.async.wait_group 0;" ::: "memory");
}
__device__ __forceinline__ u32 smem_u32(const void* p) {
    u32 a;
    asm("{ .reg .u64 t; cvta.to.shared.u64 t, %1; cvt.u32.u64 %0, t; }"
        : "=r"(a) : "l"(p));
    return a;
}

// ---------------------------------------------------------------------------
// Prep: W -> bf16 hi/lo packed, fragment-ready. Coalesced via smem transpose.
// ---------------------------------------------------------------------------
__global__ __launch_bounds__(256) void prep_w_kernel(
    const float* __restrict__ Wq, const float* __restrict__ Wk,
    const float* __restrict__ Wv)
{
    __shared__ float wt[64][65];
    const int mat = blockIdx.x / 16;
    const int kb  = blockIdx.x % 16;
    const float* W = (mat == 0) ? Wq : ((mat == 1) ? Wk : Wv);
    const int tid = threadIdx.x;

    #pragma unroll
    for (int u = 0; u < 4; u++) {
        int idx = tid + u * 256;
        int row = idx >> 4, c4 = (idx & 15) << 2;
        float4 v = *(const float4*)(W + (size_t)(kb * 64 + row) * HH + c4);
        wt[row][c4]     = v.x; wt[row][c4 + 1] = v.y;
        wt[row][c4 + 2] = v.z; wt[row][c4 + 3] = v.w;
    }
    __syncthreads();

    #pragma unroll
    for (int u = 0; u < 8; u++) {
        int idx = tid + u * 256;
        int n = idx >> 5, pj = idx & 31;
        float w0 = wt[2 * pj][n], w1 = wt[2 * pj + 1][n];
        float h0 = bfh(w0), h1 = bfh(w1);
        size_t off = (size_t)(mat * 64 + n) * 512 + kb * 32 + pj;
        g_wh[off] = pkbf(h0, h1);
        g_wl[off] = pkbf(w0 - h0, w1 - h1);
    }
}

// ---------------------------------------------------------------------------
// Fused QKV projection: M=128 x N=192, K-chunk 64, grid(128) x 512 threads.
// LDG-prefetch X + in-body convert; W cp.async double-buffered.
// B fragments via paired ldmatrix.x4 (two n-tiles per load).
// ---------------------------------------------------------------------------
#define XPK(pb)  ((pb) * 9216)
#define PW(pb)   (18432 + (pb) * 13824)
#define WSTR  36
#define PROJ_SMEM_U32 46080

__device__ __forceinline__ void stageW64(u32 sbyte, const u32* g, int tid) {
    #pragma unroll
    for (int u = 0; u < 3; u++) {
        int idx = tid + u * 512;
        int row = idx >> 3, ch = idx & 7;
        cp16(sbyte + (u32)(row * WSTR + ch * 4) * 4, g + (size_t)row * 512 + ch * 4);
    }
}
__device__ __forceinline__ void ldgX(float4 (&v)[4], const float* g, int row, int g3) {
    const float* src = g + (size_t)row * DIN + g3 * 16;
    v[0] = *(const float4*)(src);
    v[1] = *(const float4*)(src + 4);
    v[2] = *(const float4*)(src + 8);
    v[3] = *(const float4*)(src + 12);
}
__device__ __forceinline__ void convertX(u32* sxh, u32* sxl, const float4 (&v)[4],
                                         int row, int g3) {
    #pragma unroll
    for (int j = 0; j < 4; j++) {
        float h0 = bfh(v[j].x), h1 = bfh(v[j].y), h2 = bfh(v[j].z), h3 = bfh(v[j].w);
        sxh[row * WSTR + g3 * 8 + 2 * j]     = pkbf(h0, h1);
        sxh[row * WSTR + g3 * 8 + 2 * j + 1] = pkbf(h2, h3);
        sxl[row * WSTR + g3 * 8 + 2 * j]     = pkbf(v[j].x - h0, v[j].y - h1);
        sxl[row * WSTR + g3 * 8 + 2 * j + 1] = pkbf(v[j].z - h2, v[j].w - h3);
    }
}

__global__ __launch_bounds__(512) void proj_kernel(const float* __restrict__ x)
{
    extern __shared__ u32 sm[];
    const u32 sbx = smem_u32(sm);
    const int tid  = threadIdx.x;
    const int lane = tid & 31;
    const int wid  = tid >> 5;
    const int slab = wid >> 2, qc = wid & 3;
    const int rr   = lane >> 2, q = lane & 3;
    const int m0   = blockIdx.x * 128;

    const int lane7 = lane & 7;
    const int arow  = lane7 + (lane & 8);
    const int acx4  = (lane & 16) ? 16 : 0;
    // paired-B x4 addressing: lanes 16-31 take the +8-row (next n-tile) base
    const int brow  = lane7 + ((lane & 16) ? 8 : 0);
    const int bcx4  = (lane & 8) ? 16 : 0;
    const int xrow  = tid >> 2, xg3 = tid & 3;

    stageW64(sbx + (u32)PW(0) * 4,            g_wh, tid);
    stageW64(sbx + (u32)(PW(0) + 6912) * 4,   g_wl, tid);
    cp_commit();
    {
        float4 xr0[4];
        ldgX(xr0, x + (size_t)m0 * DIN, xrow, xg3);
        convertX(sm + XPK(0), sm + XPK(0) + 4608, xr0, xrow, xg3);
    }
    cp_wait0();
    __syncthreads();

    float acc[2][6][4];
    #pragma unroll
    for (int mt = 0; mt < 2; mt++)
        #pragma unroll
        for (int i = 0; i < 6; i++)
            #pragma unroll
            for (int j = 0; j < 4; j++) acc[mt][i][j] = 0.f;

    float4 xr[4];
    for (int c = 0; c < 16; c++) {
        const int pb = c & 1;
        if (c < 15) {
            stageW64(sbx + (u32)PW(pb ^ 1) * 4,          g_wh + (c + 1) * 32, tid);
            stageW64(sbx + (u32)(PW(pb ^ 1) + 6912) * 4, g_wl + (c + 1) * 32, tid);
            cp_commit();
            ldgX(xr, x + (size_t)m0 * DIN + (c + 1) * 64, xrow, xg3);
        }

        const u32 xb = (u32)XPK(pb);
        const u32 wb = (u32)PW(pb);
        u32 aH[2], aL[2];
        #pragma unroll
        for (int mt = 0; mt < 2; mt++) {
            aH[mt] = sbx + (xb + (slab * 32 + mt * 16 + arow) * WSTR) * 4 + acx4;
            aL[mt] = aH[mt] + 4608 * 4;
        }
        const u32 bH4 = sbx + (wb + (qc * 48 + brow) * WSTR) * 4 + bcx4;
        const u32 bL4 = bH4 + 6912 * 4;

        #pragma unroll
        for (int kt = 0; kt < 4; kt++) {
            u32 ah0[4], al0[4], ah1[4], al1[4];
            ldm_x4(ah0, aH[0] + kt * 32);
            ldm_x4(al0, aL[0] + kt * 32);
            ldm_x4(ah1, aH[1] + kt * 32);
            ldm_x4(al1, aL[1] + kt * 32);
            #pragma unroll
            for (int ntp = 0; ntp < 3; ntp++) {
                u32 b4h[4], b4l[4];
                ldm_x4(b4h, bH4 + ntp * (16 * WSTR * 4) + kt * 32);
                ldm_x4(b4l, bL4 + ntp * (16 * WSTR * 4) + kt * 32);
                int n0 = 2 * ntp, n1 = 2 * ntp + 1;
                mma16816(acc[0][n0], ah0, b4h);
                mma16816(acc[0][n0], ah0, b4l);
                mma16816(acc[0][n0], al0, b4h);
                mma16816(acc[1][n0], ah1, b4h);
                mma16816(acc[1][n0], ah1, b4l);
                mma16816(acc[1][n0], al1, b4h);
                mma16816(acc[0][n1], ah0, b4h + 2);
                mma16816(acc[0][n1], ah0, b4l + 2);
                mma16816(acc[0][n1], al0, b4h + 2);
                mma16816(acc[1][n1], ah1, b4h + 2);
                mma16816(acc[1][n1], ah1, b4l + 2);
                mma16816(acc[1][n1], al1, b4h + 2);
            }
        }

        if (c < 15) {
            convertX(sm + XPK(pb ^ 1), sm + XPK(pb ^ 1) + 4608, xr, xrow, xg3);
            cp_wait0();
        }
        __syncthreads();
    }

    // epilogue: q/k packed rows; v written directly transposed (shfl-paired)
    u32* const GH[2] = {g_qh, g_kh};
    u32* const GL[2] = {g_ql, g_kl};
    #pragma unroll
    for (int mt = 0; mt < 2; mt++) {
        const int row0 = m0 + slab * 32 + mt * 16 + rr;
        #pragma unroll
        for (int nt = 0; nt < 6; nt++) {
            int colb = qc * 48 + nt * 8;
            int mat = colb >> 6;
            float a0 = acc[mt][nt][0], a1 = acc[mt][nt][1];
            float a2 = acc[mt][nt][2], a3 = acc[mt][nt][3];
            if (mat < 2) {
                float s = (mat == 1) ? KSCALE : 1.f;
                a0 *= s; a1 *= s; a2 *= s; a3 *= s;
                int hqb = (colb & 63) >> 1;
                float h0 = bfh(a0), h1 = bfh(a1), h2 = bfh(a2), h3 = bfh(a3);
                GH[mat][(size_t)row0 * 32 + hqb + q]       = pkbf(h0, h1);
                GL[mat][(size_t)row0 * 32 + hqb + q]       = pkbf(a0 - h0, a1 - h1);
                GH[mat][(size_t)(row0 + 8) * 32 + hqb + q] = pkbf(h2, h3);
                GL[mat][(size_t)(row0 + 8) * 32 + hqb + q] = pkbf(a2 - h2, a3 - h3);
            } else {
                float p0 = __shfl_xor_sync(0xffffffffu, a0, 4);
                float p1 = __shfl_xor_sync(0xffffffffu, a1, 4);
                float p2 = __shfl_xor_sync(0xffffffffu, a2, 4);
                float p3 = __shfl_xor_sync(0xffffffffu, a3, 4);
                if (!(rr & 1)) {
                    int bb2 = row0 >> 11;
                    int sp  = (row0 & 2047) >> 1;
                    int vc  = (colb - 128) + 2 * q;
                    size_t base0 = ((size_t)(bb2 * 64 + vc)) * 1024;
                    size_t base1 = base0 + 1024;
                    float h, hp;
                    h = bfh(a0); hp = bfh(p0);
                    g_vth[base0 + sp] = pkbf(h, hp);
                    g_vtl[base0 + sp] = pkbf(a0 - h, p0 - hp);
                    h = bfh(a1); hp = bfh(p1);
                    g_vth[base1 + sp] = pkbf(h, hp);
                    g_vtl[base1 + sp] = pkbf(a1 - h, p1 - hp);
                    h = bfh(a2); hp = bfh(p2);
                    g_vth[base0 + sp + 4] = pkbf(h, hp);
                    g_vtl[base0 + sp + 4] = pkbf(a2 - h, p2 - hp);
                    h = bfh(a3); hp = bfh(p3);
                    g_vth[base1 + sp + 4] = pkbf(h, hp);
                    g_vtl[base1 + sp + 4] = pkbf(a3 - h, p3 - hp);
                }
            }
        }
    }
}

// ---------------------------------------------------------------------------
// Flash attention (R13 shape: 256 threads, grid(16,8)), triangle-paired CTAs,
// K fragments register-resident, exp2 softmax, paired-x4 Q/V fragment loads.
// ---------------------------------------------------------------------------
#define KOFF(t, l)  ((t) * 4608 + (l) * 2304)
#define QOFF(bf, l) (9216 + (bf) * 4608 + (l) * 2304)
#define VOFF(bf, l) (18432 + (bf) * 4608 + (l) * 2304)
#define ATTN_SMEM_U32 27904   // 111616 B

__device__ __forceinline__ void stage64(u32 sbyte, const u32* g, int gstride, int tid) {
    #pragma unroll
    for (int u = 0; u < 2; u++) {
        int idx = tid + u * 256;
        int row = idx >> 3, ch = idx & 7;
        cp16(sbyte + (u32)(row * PST + ch * 4) * 4, g + (size_t)row * gstride + ch * 4);
    }
}

__device__ __forceinline__ void online_update(
    float (&sacc)[4][4], float& m_lo, float& m_hi, float& l_lo, float& l_hi,
    float (&o)[8][4], u32 (&pah)[2][4], u32 (&pal)[2][4])
{
    float mx0 = -INFINITY, mx1 = -INFINITY;
    #pragma unroll
    for (int nt = 0; nt < 4; nt++) {
        mx0 = fmaxf(mx0, fmaxf(sacc[nt][0], sacc[nt][1]));
        mx1 = fmaxf(mx1, fmaxf(sacc[nt][2], sacc[nt][3]));
    }
    mx0 = fmaxf(mx0, __shfl_xor_sync(0xffffffffu, mx0, 1));
    mx0 = fmaxf(mx0, __shfl_xor_sync(0xffffffffu, mx0, 2));
    mx1 = fmaxf(mx1, __shfl_xor_sync(0xffffffffu, mx1, 1));
    mx1 = fmaxf(mx1, __shfl_xor_sync(0xffffffffu, mx1, 2));
    float mn0 = fmaxf(m_lo, mx0), mn1 = fmaxf(m_hi, mx1);
    float sum0 = 0.f, sum1 = 0.f;
    #pragma unroll
    for (int nt = 0; nt < 4; nt++) {
        sacc[nt][0] = ex2(fmaxf(sacc[nt][0] - mn0, -126.f));
        sacc[nt][1] = ex2(fmaxf(sacc[nt][1] - mn0, -126.f));
        sacc[nt][2] = ex2(fmaxf(sacc[nt][2] - mn1, -126.f));
        sacc[nt][3] = ex2(fmaxf(sacc[nt][3] - mn1, -126.f));
        sum0 += sacc[nt][0] + sacc[nt][1];
        sum1 += sacc[nt][2] + sacc[nt][3];
    }
    sum0 += __shfl_xor_sync(0xffffffffu, sum0, 1);
    sum0 += __shfl_xor_sync(0xffffffffu, sum0, 2);
    sum1 += __shfl_xor_sync(0xffffffffu, sum1, 1);
    sum1 += __shfl_xor_sync(0xffffffffu, sum1, 2);
    float cf0 = ex2(fmaxf(m_lo - mn0, -126.f));
    float cf1 = ex2(fmaxf(m_hi - mn1, -126.f));
    l_lo = l_lo * cf0 + sum0; l_hi = l_hi * cf1 + sum1;
    m_lo = mn0; m_hi = mn1;
    #pragma unroll
    for (int nt = 0; nt < 8; nt++) {
        o[nt][0] *= cf0; o[nt][1] *= cf0;
        o[nt][2] *= cf1; o[nt][3] *= cf1;
    }
    #pragma unroll
    for (int kp = 0; kp < 2; kp++) {
        float p00 = sacc[2*kp][0],   p01 = sacc[2*kp][1];
        float p02 = sacc[2*kp][2],   p03 = sacc[2*kp][3];
        float p10 = sacc[2*kp+1][0], p11 = sacc[2*kp+1][1];
        float p12 = sacc[2*kp+1][2], p13 = sacc[2*kp+1][3];
        float h00 = bfh(p00), h01 = bfh(p01), h02 = bfh(p02), h03 = bfh(p03);
        float h10 = bfh(p10), h11 = bfh(p11), h12 = bfh(p12), h13 = bfh(p13);
        pah[kp][0] = pkbf(h00, h01);
        pah[kp][1] = pkbf(h02, h03);
        pah[kp][2] = pkbf(h10, h11);
        pah[kp][3] = pkbf(h12, h13);
        pal[kp][0] = pkbf(p00 - h00, p01 - h01);
        pal[kp][1] = pkbf(p02 - h02, p03 - h03);
        pal[kp][2] = pkbf(p10 - h10, p11 - h11);
        pal[kp][3] = pkbf(p12 - h12, p13 - h13);
    }
}

__device__ __forceinline__ void merge_write(
    float (&o)[8][4], float m_lo, float m_hi, float l_lo, float l_hi,
    float* mlbuf, float* obuf, int slab, int half, int rr, int q,
    float* __restrict__ out, int b, int t0)
{
    __syncthreads();
    if (q == 0) {
        int base = (slab * 2 + half) * 16;
        mlbuf[(base + rr) * 2]         = m_lo;
        mlbuf[(base + rr) * 2 + 1]     = l_lo;
        mlbuf[(base + rr + 8) * 2]     = m_hi;
        mlbuf[(base + rr + 8) * 2 + 1] = l_hi;
    }
    __syncthreads();
    int ob = (slab * 2 + (1 - half)) * 16;
    float mo0 = mlbuf[(ob + rr) * 2],     lo0 = mlbuf[(ob + rr) * 2 + 1];
    float mo1 = mlbuf[(ob + rr + 8) * 2], lo1 = mlbuf[(ob + rr + 8) * 2 + 1];
    float M0 = fmaxf(m_lo, mo0), M1 = fmaxf(m_hi, mo1);
    float f0 = ex2(fmaxf(m_lo - M0, -126.f));
    float f1 = ex2(fmaxf(m_hi - M1, -126.f));
    float g0 = ex2(fmaxf(mo0 - M0, -126.f));
    float g1 = ex2(fmaxf(mo1 - M1, -126.f));
    float L0 = l_lo * f0 + lo0 * g0;
    float L1 = l_hi * f1 + lo1 * g1;
    #pragma unroll
    for (int nt = 0; nt < 8; nt++) {
        o[nt][0] *= f0; o[nt][1] *= f0;
        o[nt][2] *= f1; o[nt][3] *= f1;
    }
    if (half == 1) {
        #pragma unroll
        for (int nt = 0; nt < 8; nt++) {
            int cb = nt * 8 + 2 * q;
            obuf[(slab * 16 + rr) * 64 + cb]         = o[nt][0];
            obuf[(slab * 16 + rr) * 64 + cb + 1]     = o[nt][1];
            obuf[(slab * 16 + rr + 8) * 64 + cb]     = o[nt][2];
            obuf[(slab * 16 + rr + 8) * 64 + cb + 1] = o[nt][3];
        }
    }
    __syncthreads();
    if (half == 0) {
        float i0 = 1.f / L0, i1 = 1.f / L1;
        size_t rb = ((size_t)b * TT + t0 + slab * 16 + rr) * 64;
        #pragma unroll
        for (int nt = 0; nt < 8; nt++) {
            int cb = nt * 8 + 2 * q;
            float2 r1;
            r1.x = (o[nt][0] + obuf[(slab * 16 + rr) * 64 + cb]) * i0;
            r1.y = (o[nt][1] + obuf[(slab * 16 + rr) * 64 + cb + 1]) * i0;
            *(float2*)(out + rb + cb) = r1;
            float2 r2;
            r2.x = (o[nt][2] + obuf[(slab * 16 + rr + 8) * 64 + cb]) * i1;
            r2.y = (o[nt][3] + obuf[(slab * 16 + rr + 8) * 64 + cb + 1]) * i1;
            *(float2*)(out + rb + 8 * 64 + cb) = r2;
        }
    }
}

__global__ __launch_bounds__(256) void attn_kernel(float* __restrict__ out)
{
    extern __shared__ u32 sm[];
    float* mlbuf = (float*)(sm + 27648);
    float* obuf  = (float*)(sm + 9216);

    const int tid  = threadIdx.x;
    const int wid  = tid >> 5, lane = tid & 31;
    const int slab = wid >> 1, half = wid & 1;
    const int rr   = lane >> 2, q = lane & 3;
    const int b    = blockIdx.y;
    const int bx   = blockIdx.x;          // tile A = bx, tile B = 31-bx
    const int tB   = 31 - bx;
    const int last = tB;

    const u32 sb = smem_u32(sm);
    const int lane7 = lane & 7;
    const int arow  = lane7 + (lane & 8);
    const int acx4  = (lane & 16) ? 16 : 0;
    // paired-B x4 addressing
    const int brow  = lane7 + ((lane & 16) ? 8 : 0);
    const int bcx4  = (lane & 8) ? 16 : 0;

    // stage K (both tiles) + Q/V(st=0)
    stage64(sb + (u32)KOFF(0,0) * 4, g_kh + ((size_t)b * TT + bx * 64) * 32, 32, tid);
    stage64(sb + (u32)KOFF(0,1) * 4, g_kl + ((size_t)b * TT + bx * 64) * 32, 32, tid);
    stage64(sb + (u32)KOFF(1,0) * 4, g_kh + ((size_t)b * TT + tB * 64) * 32, 32, tid);
    stage64(sb + (u32)KOFF(1,1) * 4, g_kl + ((size_t)b * TT + tB * 64) * 32, 32, tid);
    stage64(sb + (u32)QOFF(0,0) * 4, g_qh + (size_t)b * TT * 32, 32, tid);
    stage64(sb + (u32)QOFF(0,1) * 4, g_ql + (size_t)b * TT * 32, 32, tid);
    stage64(sb + (u32)VOFF(0,0) * 4, g_vth + (size_t)b * 65536, 1024, tid);
    stage64(sb + (u32)VOFF(0,1) * 4, g_vtl + (size_t)b * 65536, 1024, tid);
    cp_commit();
    cp_wait0();
    __syncthreads();

    // hoist K fragments to registers: [tile][hl][kt][4]
    u32 kf[2][2][4][4];
    #pragma unroll
    for (int t = 0; t < 2; t++)
        #pragma unroll
        for (int l = 0; l < 2; l++) {
            u32 base = sb + (u32)(KOFF(t,l) + (slab * 16 + arow) * PST) * 4 + acx4;
            #pragma unroll
            for (int kt = 0; kt < 4; kt++)
                ldm_x4(kf[t][l][kt], base + kt * 32);
        }

    float oA[8][4], oB[8][4];
    #pragma unroll
    for (int i = 0; i < 8; i++)
        #pragma unroll
        for (int j = 0; j < 4; j++) { oA[i][j] = 0.f; oB[i][j] = 0.f; }
    float mA0 = -INFINITY, mA1 = -INFINITY, lA0 = 0.f, lA1 = 0.f;
    float mB0 = -INFINITY, mB1 = -INFINITY, lB0 = 0.f, lB1 = 0.f;

    for (int st = 0; st <= last; st++) {
        const int buf = st & 1;
        if (st > 0) { cp_wait0(); __syncthreads(); }
        if (st < last) {
            int nb = buf ^ 1, s1 = st + 1;
            stage64(sb + (u32)QOFF(nb,0) * 4, g_qh + ((size_t)b * TT + s1 * 64) * 32, 32, tid);
            stage64(sb + (u32)QOFF(nb,1) * 4, g_ql + ((size_t)b * TT + s1 * 64) * 32, 32, tid);
            stage64(sb + (u32)VOFF(nb,0) * 4, g_vth + (size_t)b * 65536 + s1 * 32, 1024, tid);
            stage64(sb + (u32)VOFF(nb,1) * 4, g_vtl + (size_t)b * 65536 + s1 * 32, 1024, tid);
            cp_commit();
        }
        const bool actA = (st <= bx);
        const u32 qB4  = sb + (u32)(QOFF(buf,0) + (half * 32 + brow) * PST) * 4 + bcx4;
        const u32 qBl4 = qB4 + 2304 * 4;
        const u32 vB4  = sb + (u32)(VOFF(buf,0) + brow * PST + half * 16) * 4 + bcx4;
        const u32 vBl4 = vB4 + 2304 * 4;

        // ---- S for both tiles (K from registers, Q via paired x4) ----
        float sA[4][4], sB4a[4][4];
        #pragma unroll
        for (int i = 0; i < 4; i++)
            #pragma unroll
            for (int j = 0; j < 4; j++) { sA[i][j] = 0.f; sB4a[i][j] = 0.f; }
        #pragma unroll
        for (int kt = 0; kt < 4; kt++) {
            #pragma unroll
            for (int ntp = 0; ntp < 2; ntp++) {
                u32 q4h[4], q4l[4];
                ldm_x4(q4h, qB4  + ntp * (16 * PST * 4) + kt * 32);
                ldm_x4(q4l, qBl4 + ntp * (16 * PST * 4) + kt * 32);
                int n0 = 2 * ntp, n1 = 2 * ntp + 1;
                if (actA) {
                    mma16816(sA[n0], kf[0][0][kt], q4h);
                    mma16816(sA[n0], kf[0][0][kt], q4l);
                    mma16816(sA[n0], kf[0][1][kt], q4h);
                    mma16816(sA[n1], kf[0][0][kt], q4h + 2);
                    mma16816(sA[n1], kf[0][0][kt], q4l + 2);
                    mma16816(sA[n1], kf[0][1][kt], q4h + 2);
                }
                mma16816(sB4a[n0], kf[1][0][kt], q4h);
                mma16816(sB4a[n0], kf[1][0][kt], q4l);
                mma16816(sB4a[n0], kf[1][1][kt], q4h);
                mma16816(sB4a[n1], kf[1][0][kt], q4h + 2);
                mma16816(sB4a[n1], kf[1][0][kt], q4l + 2);
                mma16816(sB4a[n1], kf[1][1][kt], q4h + 2);
            }
        }

        const int s0 = st * 64;
        u32 pahA[2][4], palA[2][4], pahB[2][4], palB[2][4];
        if (actA) {
            if (st == bx) {
                int tlo = bx * 64 + slab * 16 + rr, thi = tlo + 8;
                #pragma unroll
                for (int nt = 0; nt < 4; nt++) {
                    int sc = s0 + half * 32 + nt * 8 + 2 * q;
                    if (sc > tlo)     sA[nt][0] = -INFINITY;
                    if (sc + 1 > tlo) sA[nt][1] = -INFINITY;
                    if (sc > thi)     sA[nt][2] = -INFINITY;
                    if (sc + 1 > thi) sA[nt][3] = -INFINITY;
                }
            }
            online_update(sA, mA0, mA1, lA0, lA1, oA, pahA, palA);
        }
        if (st == tB) {
            int tlo = tB * 64 + slab * 16 + rr, thi = tlo + 8;
            #pragma unroll
            for (int nt = 0; nt < 4; nt++) {
                int sc = s0 + half * 32 + nt * 8 + 2 * q;
                if (sc > tlo)     sB4a[nt][0] = -INFINITY;
                if (sc + 1 > tlo) sB4a[nt][1] = -INFINITY;
                if (sc > thi)     sB4a[nt][2] = -INFINITY;
                if (sc + 1 > thi) sB4a[nt][3] = -INFINITY;
            }
        }
        online_update(sB4a, mB0, mB1, lB0, lB1, oB, pahB, palB);

        // ---- O += P.V (V via paired x4, shared between tiles) ----
        #pragma unroll
        for (int kp = 0; kp < 2; kp++) {
            #pragma unroll
            for (int ntp = 0; ntp < 4; ntp++) {
                u32 v4h[4], v4l[4];
                ldm_x4(v4h, vB4  + ntp * (16 * PST * 4) + kp * 32);
                ldm_x4(v4l, vBl4 + ntp * (16 * PST * 4) + kp * 32);
                int n0 = 2 * ntp, n1 = 2 * ntp + 1;
                if (actA) {
                    mma16816(oA[n0], pahA[kp], v4h);
                    mma16816(oA[n0], pahA[kp], v4l);
                    mma16816(oA[n0], palA[kp], v4h);
                    mma16816(oA[n1], pahA[kp], v4h + 2);
                    mma16816(oA[n1], pahA[kp], v4l + 2);
                    mma16816(oA[n1], palA[kp], v4h + 2);
                }
                mma16816(oB[n0], pahB[kp], v4h);
                mma16816(oB[n0], pahB[kp], v4l);
                mma16816(oB[n0], palB[kp], v4h);
                mma16816(oB[n1], pahB[kp], v4h + 2);
                mma16816(oB[n1], pahB[kp], v4l + 2);
                mma16816(oB[n1], palB[kp], v4h + 2);
            }
        }
    }

    merge_write(oA, mA0, mA1, lA0, lA1, mlbuf, obuf, slab, half, rr, q, out, b, bx * 64);
    merge_write(oB, mB0, mB1, lB0, lB1, mlbuf, obuf, slab, half, rr, q, out, b, tB * 64);
}

// ---------------------------------------------------------------------------
extern "C" void kernel_launch(void* const* d_in, const int* in_sizes, int n_in,
                              void* d_out, int out_size)
{
    const float* x  = (const float*)d_in[0];
    const float* Wq = (const float*)d_in[1];
    const float* Wk = (const float*)d_in[2];
    const float* Wv = (const float*)d_in[3];
    float* out = (float*)d_out;

    prep_w_kernel<<<48, 256>>>(Wq, Wk, Wv);

    cudaFuncSetAttribute(proj_kernel,
                         cudaFuncAttributeMaxDynamicSharedMemorySize,
                         PROJ_SMEM_U32 * 4);
    proj_kernel<<<128, 512, PROJ_SMEM_U32 * 4>>>(x);

    cudaFuncSetAttribute(attn_kernel,
                         cudaFuncAttributeMaxDynamicSharedMemorySize,
                         ATTN_SMEM_U32 * 4);
    dim3 grid(16, BB);
    attn_kernel<<<grid, 256, ATTN_SMEM_U32 * 4>>>(out);
}